// round 1
// baseline (speedup 1.0000x reference)
#include <cuda_runtime.h>
#include <math.h>

// ---------------- problem constants ----------------
#define Bb   256
#define Ss   32
#define VFd  512
#define IFd  256
#define Ff   768          // F = VF + IF
#define Hh   1024
#define Ll   2
#define Kk   8
#define MB   (Ll*Bb)      // 512 rows for the ODE state GEMMs
#define G3F  (3*Ff)       // 2304

// ---------------- persistent device scratch (no allocs allowed) ----------------
__device__ float g_x   [Ss*Bb*Ff];     // fused input, [S,B,F]
__device__ float g_dt  [Ss*Bb];        // dt transposed, [S,B]
__device__ float g_Y   [Ll*Bb*Ff];     // hidden state [L,B,F]
__device__ float g_h1  [MB*Hh];
__device__ float g_h2  [MB*Hh];
__device__ float g_gx0 [Ss*Bb*G3F];    // precomputed layer-0 GRU input proj [S,B,3F]
__device__ float g_gh  [Bb*G3F];
__device__ float g_gx1 [Bb*G3F];
__device__ float g_x1  [Bb*Ff];        // layer-0 output -> layer-1 input
__device__ float g_out [Ss*Bb*Ff];     // sequence outputs [S,B,F]
__device__ float g_hid [Ss*Bb*128];    // regressor hidden

// ---------------- prep kernels ----------------
__global__ void k_prep_x(const float* __restrict__ fv, const float* __restrict__ fi) {
    int stride = gridDim.x * blockDim.x;
    int total  = Ss*Bb*Ff;
    for (int idx = blockIdx.x*blockDim.x + threadIdx.x; idx < total; idx += stride) {
        int f  = idx % Ff;
        int sb = idx / Ff;
        int b  = sb % Bb;
        int s  = sb / Bb;
        g_x[idx] = (f < VFd) ? fv[(b*Ss + s)*VFd + f]
                             : fi[(b*Ss + s)*IFd + (f - VFd)];
    }
}

__global__ void k_prep_misc(const float* __restrict__ ts) {
    int stride = gridDim.x * blockDim.x;
    for (int i = blockIdx.x*blockDim.x + threadIdx.x; i < Ll*Bb*Ff; i += stride)
        g_Y[i] = 0.0f;
    for (int i = blockIdx.x*blockDim.x + threadIdx.x; i < Ss*Bb; i += stride) {
        int s = i / Bb, b = i % Bb;
        g_dt[i] = (s < Ss-1) ? (ts[b*Ss + s + 1] - ts[b*Ss + s]) : 0.0f;
    }
}

// ---------------- generic NT GEMM with fused epilogues ----------------
// C[M,N] = epi( A[M,K] * B[N,K]^T + bias[N] )
// Tiles: 64x64, 256 threads, 4x4 per thread, BK=16. M,N % 64 == 0, K % 16 == 0.
enum { EPI_STORE = 0, EPI_TANH = 1, EPI_ODE = 2, EPI_LRELU = 3 };

template<int EPI>
__global__ void __launch_bounds__(256)
k_gemm(const float* __restrict__ A, int lda,
       const float* __restrict__ Bm, int ldb,
       const float* __restrict__ bias,
       float* __restrict__ C, int ldc,
       int Kd, const float* __restrict__ dtv)
{
    __shared__ float As[16][68];
    __shared__ float Bs[16][68];

    int tid  = threadIdx.x;
    int m0   = blockIdx.y << 6;
    int n0   = blockIdx.x << 6;
    int lrow = tid >> 2;          // 0..63
    int kq   = (tid & 3) << 2;    // 0,4,8,12
    int tx   = tid & 15, ty = tid >> 4;

    const float* Ap = A  + (size_t)(m0 + lrow) * lda + kq;
    const float* Bp = Bm + (size_t)(n0 + lrow) * ldb + kq;

    float acc[4][4];
#pragma unroll
    for (int i = 0; i < 4; i++)
#pragma unroll
        for (int j = 0; j < 4; j++) acc[i][j] = 0.0f;

    for (int k0 = 0; k0 < Kd; k0 += 16) {
        float4 av = *(const float4*)(Ap + k0);
        float4 bv = *(const float4*)(Bp + k0);
        As[kq  ][lrow] = av.x; As[kq+1][lrow] = av.y;
        As[kq+2][lrow] = av.z; As[kq+3][lrow] = av.w;
        Bs[kq  ][lrow] = bv.x; Bs[kq+1][lrow] = bv.y;
        Bs[kq+2][lrow] = bv.z; Bs[kq+3][lrow] = bv.w;
        __syncthreads();
#pragma unroll
        for (int kk = 0; kk < 16; kk++) {
            float a4[4], b4[4];
            *(float4*)a4 = *(const float4*)&As[kk][ty << 2];
            *(float4*)b4 = *(const float4*)&Bs[kk][tx << 2];
#pragma unroll
            for (int i = 0; i < 4; i++)
#pragma unroll
                for (int j = 0; j < 4; j++)
                    acc[i][j] += a4[i] * b4[j];
        }
        __syncthreads();
    }

    int nb = n0 + (tx << 2);
    float bb4[4];
#pragma unroll
    for (int j = 0; j < 4; j++) bb4[j] = bias[nb + j];

#pragma unroll
    for (int i = 0; i < 4; i++) {
        int m = m0 + (ty << 2) + i;
        float* Crow = C + (size_t)m * ldc + nb;
        float sub = 0.0f;
        if (EPI == EPI_ODE) sub = dtv[m & (Bb - 1)] * (1.0f / Kk);
#pragma unroll
        for (int j = 0; j < 4; j++) {
            float v = acc[i][j] + bb4[j];
            if (EPI == EPI_TANH)  v = tanhf(v);
            if (EPI == EPI_LRELU) v = (v > 0.0f) ? v : 0.1f * v;
            if (EPI == EPI_ODE)   Crow[j] += sub * v;
            else                  Crow[j]  = v;
        }
    }
}

// ---------------- GRU elementwise combine ----------------
__global__ void k_gru(const float* __restrict__ gx, const float* __restrict__ gh,
                      float* __restrict__ h, float* __restrict__ xout)
{
    int idx = blockIdx.x*blockDim.x + threadIdx.x;
    if (idx >= Bb*Ff) return;
    int b = idx / Ff, f = idx % Ff;
    int o = b*G3F + f;
    float r  = 1.0f / (1.0f + expf(-(gx[o]        + gh[o]       )));
    float z  = 1.0f / (1.0f + expf(-(gx[o + Ff]   + gh[o + Ff]  )));
    float n  = tanhf(gx[o + 2*Ff] + r * gh[o + 2*Ff]);
    float hp = h[idx];
    float hn = (1.0f - z) * n + z * hp;
    h[idx]    = hn;
    xout[idx] = hn;
}

// ---------------- regressor second layer (N=6) ----------------
__global__ void k_pose(const float* __restrict__ W2, const float* __restrict__ b2,
                       float* __restrict__ outp)
{
    int idx = blockIdx.x*blockDim.x + threadIdx.x;
    if (idx >= Ss*Bb*6) return;
    int n = idx % 6;
    int m = idx / 6;            // m = s*B + b
    int b = m % Bb, s = m / Bb;
    const float* hrow = g_hid + (size_t)m * 128;
    const float* wrow = W2   + n * 128;
    float acc = b2[n];
#pragma unroll 8
    for (int k = 0; k < 128; k++) acc += hrow[k] * wrow[k];
    outp[(b*Ss + s)*6 + n] = acc;
}

__global__ void k_copyY(float* __restrict__ outp) {
    int stride = gridDim.x * blockDim.x;
    for (int i = blockIdx.x*blockDim.x + threadIdx.x; i < Ll*Bb*Ff; i += stride)
        outp[i] = g_Y[i];
}

// ---------------- launch ----------------
extern "C" void kernel_launch(void* const* d_in, const int* in_sizes, int n_in,
                              void* d_out, int out_size)
{
    const float* fv  = (const float*)d_in[0];
    const float* fi  = (const float*)d_in[1];
    const float* ts  = (const float*)d_in[2];
    const float* W0  = (const float*)d_in[3];
    const float* b0  = (const float*)d_in[4];
    const float* W1  = (const float*)d_in[5];
    const float* b1  = (const float*)d_in[6];
    const float* W2o = (const float*)d_in[7];
    const float* b2o = (const float*)d_in[8];
    const float* gWx = (const float*)d_in[9];
    const float* gWh = (const float*)d_in[10];
    const float* gbx = (const float*)d_in[11];
    const float* gbh = (const float*)d_in[12];
    const float* rW1 = (const float*)d_in[13];
    const float* rb1 = (const float*)d_in[14];
    const float* rW2 = (const float*)d_in[15];
    const float* rb2 = (const float*)d_in[16];

    float *px, *pdt, *pY, *ph1, *ph2, *pgx0, *pgh, *pgx1, *px1, *pout, *phid;
    cudaGetSymbolAddress((void**)&px,   g_x);
    cudaGetSymbolAddress((void**)&pdt,  g_dt);
    cudaGetSymbolAddress((void**)&pY,   g_Y);
    cudaGetSymbolAddress((void**)&ph1,  g_h1);
    cudaGetSymbolAddress((void**)&ph2,  g_h2);
    cudaGetSymbolAddress((void**)&pgx0, g_gx0);
    cudaGetSymbolAddress((void**)&pgh,  g_gh);
    cudaGetSymbolAddress((void**)&pgx1, g_gx1);
    cudaGetSymbolAddress((void**)&px1,  g_x1);
    cudaGetSymbolAddress((void**)&pout, g_out);
    cudaGetSymbolAddress((void**)&phid, g_hid);

    k_prep_x<<<512, 256>>>(fv, fi);
    k_prep_misc<<<512, 256>>>(ts);

    // hoisted layer-0 GRU input projection: [S*B,3F] = x @ Wx0^T + bx0
    k_gemm<EPI_STORE><<<dim3(G3F/64, (Ss*Bb)/64), 256>>>(
        px, Ff, gWx, Ff, gbx, pgx0, G3F, Ff, nullptr);

    const int gruBlocks = (Bb*Ff + 255) / 256;

    for (int t = 0; t < Ss; t++) {
        // ODE: K Euler substeps on Y[L,B,F] (treated as one [512,F] matrix)
        for (int k = 0; k < Kk; k++) {
            k_gemm<EPI_TANH><<<dim3(Hh/64, MB/64), 256>>>(
                pY, Ff, W0, Ff, b0, ph1, Hh, Ff, nullptr);
            k_gemm<EPI_TANH><<<dim3(Hh/64, MB/64), 256>>>(
                ph1, Hh, W1, Hh, b1, ph2, Hh, Hh, nullptr);
            k_gemm<EPI_ODE><<<dim3(Ff/64, MB/64), 256>>>(
                ph2, Hh, W2o, Hh, b2o, pY, Ff, Hh, pdt + t*Bb);
        }
        // GRU layer 0: gh = Y0 @ Wh0^T + bh0, combine with precomputed gx0
        k_gemm<EPI_STORE><<<dim3(G3F/64, Bb/64), 256>>>(
            pY, Ff, gWh, Ff, gbh, pgh, G3F, Ff, nullptr);
        k_gru<<<gruBlocks, 256>>>(pgx0 + (size_t)t*Bb*G3F, pgh, pY, px1);

        // GRU layer 1
        k_gemm<EPI_STORE><<<dim3(G3F/64, Bb/64), 256>>>(
            px1, Ff, gWx + (size_t)G3F*Ff, Ff, gbx + G3F, pgx1, G3F, Ff, nullptr);
        k_gemm<EPI_STORE><<<dim3(G3F/64, Bb/64), 256>>>(
            pY + Bb*Ff, Ff, gWh + (size_t)G3F*Ff, Ff, gbh + G3F, pgh, G3F, Ff, nullptr);
        k_gru<<<gruBlocks, 256>>>(pgx1, pgh, pY + Bb*Ff, pout + (size_t)t*Bb*Ff);
    }

    // regressor: hid = leaky_relu(out @ rW1^T + rb1, 0.1); pose = hid @ rW2^T + rb2
    k_gemm<EPI_LRELU><<<dim3(128/64, (Ss*Bb)/64), 256>>>(
        pout, Ff, rW1, Ff, rb1, phid, 128, Ff, nullptr);
    k_pose<<<(Ss*Bb*6 + 127)/128, 128>>>(rW2, rb2, (float*)d_out);

    if (out_size >= Ss*Bb*6 + Ll*Bb*Ff)
        k_copyY<<<768, 256>>>((float*)d_out + Ss*Bb*6);
}

// round 3
// speedup vs baseline: 2.5878x; 2.5878x over previous
#include <cuda_runtime.h>
#include <cuda_bf16.h>
#include <math.h>
#include <stdint.h>

// ---------------- problem constants ----------------
#define Bb   256
#define Ss   32
#define VFd  512
#define IFd  256
#define Ff   768
#define Hh   1024
#define Ll   2
#define Kk   8
#define MB   (Ll*Bb)
#define G3F  (3*Ff)

// ---------------- GEMM tiling ----------------
#define BM 64
#define BN 64
#define BK 32
#define ROWB   80            // smem row stride in bytes (40 bf16 = 5x16B, conflict-free)
#define PLANE  (64*ROWB)     // 5120 B, one 64x32 bf16 tile
#define STAGE_BYTES (4*PLANE) // Ahi,Alo,Bhi,Blo = 20480 B
#define NSTAGE 3
#define SMEM_TOTAL (NSTAGE*STAGE_BYTES)  // 61440

// ---------------- persistent device scratch ----------------
__device__ __align__(16) float g_dt  [Ss*Bb];
__device__ __align__(16) float g_Y   [MB*Ff];
__device__ __align__(16) __nv_bfloat16 g_Yhi [MB*Ff];
__device__ __align__(16) __nv_bfloat16 g_Ylo [MB*Ff];
__device__ __align__(16) __nv_bfloat16 g_xhi [Ss*Bb*Ff];
__device__ __align__(16) __nv_bfloat16 g_xlo [Ss*Bb*Ff];
__device__ __align__(16) __nv_bfloat16 g_h1hi[MB*Hh];
__device__ __align__(16) __nv_bfloat16 g_h1lo[MB*Hh];
__device__ __align__(16) __nv_bfloat16 g_h2hi[MB*Hh];
__device__ __align__(16) __nv_bfloat16 g_h2lo[MB*Hh];
__device__ __align__(16) __nv_bfloat16 g_x1hi[Bb*Ff];
__device__ __align__(16) __nv_bfloat16 g_x1lo[Bb*Ff];
__device__ __align__(16) __nv_bfloat16 g_outhi[Ss*Bb*Ff];
__device__ __align__(16) __nv_bfloat16 g_outlo[Ss*Bb*Ff];
__device__ __align__(16) float g_gx0 [Ss*Bb*G3F];
__device__ __align__(16) float g_gh  [Bb*G3F];
__device__ __align__(16) float g_gx1 [Bb*G3F];
__device__ __align__(16) float g_hid [Ss*Bb*128];
// weight splits
__device__ __align__(16) __nv_bfloat16 g_W0h[Hh*Ff],  g_W0l[Hh*Ff];
__device__ __align__(16) __nv_bfloat16 g_W1h[Hh*Hh],  g_W1l[Hh*Hh];
__device__ __align__(16) __nv_bfloat16 g_W2h[Ff*Hh],  g_W2l[Ff*Hh];
__device__ __align__(16) __nv_bfloat16 g_Wxh[Ll*G3F*Ff], g_Wxl[Ll*G3F*Ff];
__device__ __align__(16) __nv_bfloat16 g_Whh[Ll*G3F*Ff], g_Whl[Ll*G3F*Ff];
__device__ __align__(16) __nv_bfloat16 g_rW1h[128*Ff], g_rW1l[128*Ff];

__device__ __forceinline__ void split_bf(float v, __nv_bfloat16& h, __nv_bfloat16& l) {
    h = __float2bfloat16_rn(v);
    l = __float2bfloat16_rn(v - __bfloat162float(h));
}

__device__ __forceinline__ uint32_t smem_u32(const void* p) {
    uint32_t a;
    asm("{ .reg .u64 t; cvta.to.shared.u64 t, %1; cvt.u32.u64 %0, t; }" : "=r"(a) : "l"(p));
    return a;
}
__device__ __forceinline__ void cp16(uint32_t dst, const void* src) {
    asm volatile("cp.async.cg.shared.global [%0], [%1], 16;" :: "r"(dst), "l"(src));
}
__device__ __forceinline__ void ldm_x4(uint32_t addr, uint32_t r[4]) {
    asm volatile("ldmatrix.sync.aligned.m8n8.x4.shared.b16 {%0,%1,%2,%3}, [%4];"
                 : "=r"(r[0]), "=r"(r[1]), "=r"(r[2]), "=r"(r[3]) : "r"(addr));
}
__device__ __forceinline__ void mma16816(float d[4], const uint32_t a[4],
                                         uint32_t b0, uint32_t b1) {
    asm volatile("mma.sync.aligned.m16n8k16.row.col.f32.bf16.bf16.f32 "
                 "{%0,%1,%2,%3}, {%4,%5,%6,%7}, {%8,%9}, {%0,%1,%2,%3};"
                 : "+f"(d[0]), "+f"(d[1]), "+f"(d[2]), "+f"(d[3])
                 : "r"(a[0]), "r"(a[1]), "r"(a[2]), "r"(a[3]), "r"(b0), "r"(b1));
}

// ---------------- prep kernels ----------------
__global__ void k_split(const float* __restrict__ src, __nv_bfloat16* __restrict__ hi,
                        __nv_bfloat16* __restrict__ lo, int n) {
    int stride = gridDim.x * blockDim.x;
    for (int i = blockIdx.x*blockDim.x + threadIdx.x; i < n; i += stride)
        split_bf(src[i], hi[i], lo[i]);
}

__global__ void k_prep_x(const float* __restrict__ fv, const float* __restrict__ fi) {
    int stride = gridDim.x * blockDim.x;
    int total  = Ss*Bb*Ff;
    for (int idx = blockIdx.x*blockDim.x + threadIdx.x; idx < total; idx += stride) {
        int f  = idx % Ff;
        int sb = idx / Ff;
        int b  = sb % Bb, s = sb / Bb;
        float v = (f < VFd) ? fv[(b*Ss + s)*VFd + f] : fi[(b*Ss + s)*IFd + (f - VFd)];
        split_bf(v, g_xhi[idx], g_xlo[idx]);
    }
}

__global__ void k_prep_misc(const float* __restrict__ ts) {
    int stride = gridDim.x * blockDim.x;
    for (int i = blockIdx.x*blockDim.x + threadIdx.x; i < MB*Ff; i += stride) {
        g_Y[i] = 0.0f; g_Yhi[i] = __float2bfloat16(0.0f); g_Ylo[i] = __float2bfloat16(0.0f);
    }
    for (int i = blockIdx.x*blockDim.x + threadIdx.x; i < Ss*Bb; i += stride) {
        int s = i / Bb, b = i % Bb;
        g_dt[i] = (s < Ss-1) ? (ts[b*Ss + s + 1] - ts[b*Ss + s]) : 0.0f;
    }
}

// ---------------- bf16x3 HMMA GEMM: C[M,N] = epi(A*B^T + bias) ----------------
// A stored as hi/lo bf16 planes [M,K] row-major; B as hi/lo [N,K] row-major.
enum { EPI_STORE = 0, EPI_TANH = 1, EPI_ODE = 2, EPI_LRELU = 3 };

template<int EPI>
__global__ void __launch_bounds__(128)
k_mgemm(const __nv_bfloat16* __restrict__ Ahi, const __nv_bfloat16* __restrict__ Alo, int lda,
        const __nv_bfloat16* __restrict__ Bhi, const __nv_bfloat16* __restrict__ Blo, int ldb,
        const float* __restrict__ bias,
        float* __restrict__ Cf, __nv_bfloat16* __restrict__ Chi, __nv_bfloat16* __restrict__ Clo,
        int ldc, int Kd, const float* __restrict__ dtv)
{
    extern __shared__ char smem[];
    const uint32_t smem_base = smem_u32(smem);
    const int tid  = threadIdx.x;
    const int wid  = tid >> 5, lane = tid & 31;
    const int m0   = blockIdx.y << 6, n0 = blockIdx.x << 6;
    const int warp_m = wid & 1, warp_n = wid >> 1;

    // per-thread global load coords (2 iterations x 4 planes)
    const int l_row0 = tid >> 2;            // 0..31
    const int l_kq   = (tid & 3) * 8;       // 0,8,16,24

    auto issue_stage = [&](int c) {
        const int k0 = c * BK;
        const uint32_t sb = smem_base + (uint32_t)(c % NSTAGE) * STAGE_BYTES;
#pragma unroll
        for (int i = 0; i < 2; i++) {
            const int row = l_row0 + i * 32;
            const uint32_t dst = sb + (uint32_t)row * ROWB + l_kq * 2;
            const size_t ga = (size_t)(m0 + row) * lda + k0 + l_kq;
            const size_t gb = (size_t)(n0 + row) * ldb + k0 + l_kq;
            cp16(dst,             Ahi + ga);
            cp16(dst + PLANE,     Alo + ga);
            cp16(dst + 2*PLANE,   Bhi + gb);
            cp16(dst + 3*PLANE,   Blo + gb);
        }
        asm volatile("cp.async.commit_group;");
    };

    float acc[2][4][4];
#pragma unroll
    for (int mi = 0; mi < 2; mi++)
#pragma unroll
        for (int nj = 0; nj < 4; nj++)
#pragma unroll
            for (int e = 0; e < 4; e++) acc[mi][nj][e] = 0.0f;

    const int nc = Kd / BK;
    issue_stage(0);
    issue_stage(1);

    // fragment smem offsets
    const int arow  = lane & 15, acol8 = (lane >> 4) * 8;
    const int brow  = ((lane >> 4) & 1) * 8 + (lane & 7);
    const int bcol8 = ((lane >> 3) & 1) * 8;
    const uint32_t aoff = (uint32_t)(warp_m*32 + arow) * ROWB + acol8 * 2;
    const uint32_t boff = 2*PLANE + (uint32_t)(warp_n*32 + brow) * ROWB + bcol8 * 2;

    for (int c = 0; c < nc; c++) {
        if (c + 1 < nc) { asm volatile("cp.async.wait_group 1;"); }
        else            { asm volatile("cp.async.wait_group 0;"); }
        __syncthreads();
        if (c + 2 < nc) issue_stage(c + 2);

        const uint32_t sb = smem_base + (uint32_t)(c % NSTAGE) * STAGE_BYTES;
#pragma unroll
        for (int kk = 0; kk < 2; kk++) {
            uint32_t ah[2][4], al[2][4], bh[2][4], bl[2][4];
#pragma unroll
            for (int mi = 0; mi < 2; mi++) {
                uint32_t ad = sb + aoff + mi*16*ROWB + kk*32;
                ldm_x4(ad,          ah[mi]);
                ldm_x4(ad + PLANE,  al[mi]);
            }
#pragma unroll
            for (int nj = 0; nj < 2; nj++) {
                uint32_t bd = sb + boff + nj*16*ROWB + kk*32;
                ldm_x4(bd,          bh[nj]);
                ldm_x4(bd + PLANE,  bl[nj]);
            }
            // bh[nj] regs: r0=(n0-7,k0-7) r1=(n0-7,k8-15) r2=(n8-15,k0-7) r3=(n8-15,k8-15)
#pragma unroll
            for (int mi = 0; mi < 2; mi++)
#pragma unroll
                for (int n8 = 0; n8 < 4; n8++) {
                    const int nj = n8 >> 1, hf = (n8 & 1) << 1;
                    mma16816(acc[mi][n8], ah[mi], bh[nj][hf], bh[nj][hf+1]); // hi*hi
                    mma16816(acc[mi][n8], al[mi], bh[nj][hf], bh[nj][hf+1]); // lo*hi
                    mma16816(acc[mi][n8], ah[mi], bl[nj][hf], bl[nj][hf+1]); // hi*lo
                }
        }
        __syncthreads();
    }

    // ---- epilogue ----
    const int rbase = lane >> 2;           // 0..7
    const int cbase = (lane & 3) * 2;
#pragma unroll
    for (int mi = 0; mi < 2; mi++) {
#pragma unroll
        for (int n8 = 0; n8 < 4; n8++) {
#pragma unroll
            for (int half = 0; half < 2; half++) {   // accum rows +0 / +8
                const int m = m0 + warp_m*32 + mi*16 + rbase + half*8;
                const int n = n0 + warp_n*32 + n8*8 + cbase;
                float v0 = acc[mi][n8][half*2 + 0] + __ldg(bias + n);
                float v1 = acc[mi][n8][half*2 + 1] + __ldg(bias + n + 1);
                if (EPI == EPI_TANH)  { v0 = tanhf(v0); v1 = tanhf(v1); }
                if (EPI == EPI_LRELU) { v0 = (v0 > 0.f) ? v0 : 0.1f*v0;
                                        v1 = (v1 > 0.f) ? v1 : 0.1f*v1; }
                const size_t o = (size_t)m * ldc + n;
                if (EPI == EPI_ODE) {
                    const float sub = __ldg(dtv + (m & (Bb - 1))) * (1.0f / Kk);
                    float2 y = *(float2*)(Cf + o);
                    y.x += sub * v0; y.y += sub * v1;
                    *(float2*)(Cf + o) = y;
                    __nv_bfloat16 h0, l0, h1, l1;
                    split_bf(y.x, h0, l0); split_bf(y.y, h1, l1);
                    *(__nv_bfloat162*)(Chi + o) = __nv_bfloat162(h0, h1);
                    *(__nv_bfloat162*)(Clo + o) = __nv_bfloat162(l0, l1);
                } else if (EPI == EPI_TANH) {
                    __nv_bfloat16 h0, l0, h1, l1;
                    split_bf(v0, h0, l0); split_bf(v1, h1, l1);
                    *(__nv_bfloat162*)(Chi + o) = __nv_bfloat162(h0, h1);
                    *(__nv_bfloat162*)(Clo + o) = __nv_bfloat162(l0, l1);
                } else {
                    *(float2*)(Cf + o) = make_float2(v0, v1);
                }
            }
        }
    }
}

// ---------------- GRU elementwise combine ----------------
__global__ void k_gru(const float* __restrict__ gx, const float* __restrict__ gh,
                      float* __restrict__ h,
                      __nv_bfloat16* __restrict__ hhi, __nv_bfloat16* __restrict__ hlo,
                      __nv_bfloat16* __restrict__ xhi, __nv_bfloat16* __restrict__ xlo)
{
    int idx = blockIdx.x*blockDim.x + threadIdx.x;
    if (idx >= Bb*Ff) return;
    int b = idx / Ff, f = idx % Ff;
    int o = b*G3F + f;
    float r  = 1.0f / (1.0f + expf(-(gx[o]        + gh[o]       )));
    float z  = 1.0f / (1.0f + expf(-(gx[o + Ff]   + gh[o + Ff]  )));
    float n  = tanhf(gx[o + 2*Ff] + r * gh[o + 2*Ff]);
    float hn = (1.0f - z) * n + z * h[idx];
    h[idx] = hn;
    __nv_bfloat16 hi, lo;
    split_bf(hn, hi, lo);
    hhi[idx] = hi; hlo[idx] = lo;
    xhi[idx] = hi; xlo[idx] = lo;
}

// ---------------- regressor second layer (N=6) ----------------
__global__ void k_pose(const float* __restrict__ W2, const float* __restrict__ b2,
                       float* __restrict__ outp)
{
    int idx = blockIdx.x*blockDim.x + threadIdx.x;
    if (idx >= Ss*Bb*6) return;
    int n = idx % 6;
    int m = idx / 6;
    int b = m % Bb, s = m / Bb;
    const float* hrow = g_hid + (size_t)m * 128;
    const float* wrow = W2 + n * 128;
    float acc = b2[n];
#pragma unroll 8
    for (int k = 0; k < 128; k++) acc += hrow[k] * wrow[k];
    outp[(b*Ss + s)*6 + n] = acc;
}

__global__ void k_copyY(float* __restrict__ outp) {
    int stride = gridDim.x * blockDim.x;
    for (int i = blockIdx.x*blockDim.x + threadIdx.x; i < MB*Ff; i += stride)
        outp[i] = g_Y[i];
}

// ---------------- launch ----------------
extern "C" void kernel_launch(void* const* d_in, const int* in_sizes, int n_in,
                              void* d_out, int out_size)
{
    const float* fv  = (const float*)d_in[0];
    const float* fi  = (const float*)d_in[1];
    const float* ts  = (const float*)d_in[2];
    const float* W0  = (const float*)d_in[3];
    const float* b0  = (const float*)d_in[4];
    const float* W1  = (const float*)d_in[5];
    const float* b1  = (const float*)d_in[6];
    const float* W2o = (const float*)d_in[7];
    const float* b2o = (const float*)d_in[8];
    const float* gWx = (const float*)d_in[9];
    const float* gWh = (const float*)d_in[10];
    const float* gbx = (const float*)d_in[11];
    const float* gbh = (const float*)d_in[12];
    const float* rW1 = (const float*)d_in[13];
    const float* rb1 = (const float*)d_in[14];
    const float* rW2 = (const float*)d_in[15];
    const float* rb2 = (const float*)d_in[16];

    cudaFuncSetAttribute(k_mgemm<EPI_STORE>, cudaFuncAttributeMaxDynamicSharedMemorySize, SMEM_TOTAL);
    cudaFuncSetAttribute(k_mgemm<EPI_TANH >, cudaFuncAttributeMaxDynamicSharedMemorySize, SMEM_TOTAL);
    cudaFuncSetAttribute(k_mgemm<EPI_ODE  >, cudaFuncAttributeMaxDynamicSharedMemorySize, SMEM_TOTAL);
    cudaFuncSetAttribute(k_mgemm<EPI_LRELU>, cudaFuncAttributeMaxDynamicSharedMemorySize, SMEM_TOTAL);

#define SYM(p, s) float* p; cudaGetSymbolAddress((void**)&p, s)
#define SYMB(p, s) __nv_bfloat16* p; cudaGetSymbolAddress((void**)&p, s)
    SYM(pdt, g_dt); SYM(pY, g_Y);
    SYMB(pYhi, g_Yhi); SYMB(pYlo, g_Ylo);
    SYMB(pxhi, g_xhi); SYMB(pxlo, g_xlo);
    SYMB(ph1hi, g_h1hi); SYMB(ph1lo, g_h1lo);
    SYMB(ph2hi, g_h2hi); SYMB(ph2lo, g_h2lo);
    SYMB(px1hi, g_x1hi); SYMB(px1lo, g_x1lo);
    SYMB(pouthi, g_outhi); SYMB(poutlo, g_outlo);
    SYM(pgx0, g_gx0); SYM(pgh, g_gh); SYM(pgx1, g_gx1); SYM(phid, g_hid);
    SYMB(pW0h, g_W0h); SYMB(pW0l, g_W0l);
    SYMB(pW1h, g_W1h); SYMB(pW1l, g_W1l);
    SYMB(pW2h, g_W2h); SYMB(pW2l, g_W2l);
    SYMB(pWxh, g_Wxh); SYMB(pWxl, g_Wxl);
    SYMB(pWhh, g_Whh); SYMB(pWhl, g_Whl);
    SYMB(prW1h, g_rW1h); SYMB(prW1l, g_rW1l);
#undef SYM
#undef SYMB

    // weight splits (deterministic; recomputed every call)
    k_split<<<256, 256>>>(W0,  pW0h,  pW0l,  Hh*Ff);
    k_split<<<256, 256>>>(W1,  pW1h,  pW1l,  Hh*Hh);
    k_split<<<256, 256>>>(W2o, pW2h,  pW2l,  Ff*Hh);
    k_split<<<256, 256>>>(gWx, pWxh,  pWxl,  Ll*G3F*Ff);
    k_split<<<256, 256>>>(gWh, pWhh,  pWhl,  Ll*G3F*Ff);
    k_split<<<64,  256>>>(rW1, prW1h, prW1l, 128*Ff);

    k_prep_x<<<512, 256>>>(fv, fi);
    k_prep_misc<<<512, 256>>>(ts);

    // hoisted layer-0 GRU input projection: gx0[S*B,3F] = x @ Wx0^T + bx0
    k_mgemm<EPI_STORE><<<dim3(G3F/BN, (Ss*Bb)/BM), 128, SMEM_TOTAL>>>(
        pxhi, pxlo, Ff, pWxh, pWxl, Ff, gbx,
        pgx0, nullptr, nullptr, G3F, Ff, nullptr);

    const int gruBlocks = (Bb*Ff + 255) / 256;

    for (int t = 0; t < Ss; t++) {
        for (int k = 0; k < Kk; k++) {
            k_mgemm<EPI_TANH><<<dim3(Hh/BN, MB/BM), 128, SMEM_TOTAL>>>(
                pYhi, pYlo, Ff, pW0h, pW0l, Ff, b0,
                nullptr, ph1hi, ph1lo, Hh, Ff, nullptr);
            k_mgemm<EPI_TANH><<<dim3(Hh/BN, MB/BM), 128, SMEM_TOTAL>>>(
                ph1hi, ph1lo, Hh, pW1h, pW1l, Hh, b1,
                nullptr, ph2hi, ph2lo, Hh, Hh, nullptr);
            k_mgemm<EPI_ODE><<<dim3(Ff/BN, MB/BM), 128, SMEM_TOTAL>>>(
                ph2hi, ph2lo, Hh, pW2h, pW2l, Hh, b2o,
                pY, pYhi, pYlo, Ff, Hh, pdt + t*Bb);
        }
        // GRU layer 0
        k_mgemm<EPI_STORE><<<dim3(G3F/BN, Bb/BM), 128, SMEM_TOTAL>>>(
            pYhi, pYlo, Ff, pWhh, pWhl, Ff, gbh,
            pgh, nullptr, nullptr, G3F, Ff, nullptr);
        k_gru<<<gruBlocks, 256>>>(pgx0 + (size_t)t*Bb*G3F, pgh,
                                  pY, pYhi, pYlo, px1hi, px1lo);
        // GRU layer 1
        k_mgemm<EPI_STORE><<<dim3(G3F/BN, Bb/BM), 128, SMEM_TOTAL>>>(
            px1hi, px1lo, Ff, pWxh + (size_t)G3F*Ff, pWxl + (size_t)G3F*Ff, Ff, gbx + G3F,
            pgx1, nullptr, nullptr, G3F, Ff, nullptr);
        k_mgemm<EPI_STORE><<<dim3(G3F/BN, Bb/BM), 128, SMEM_TOTAL>>>(
            pYhi + Bb*Ff, pYlo + Bb*Ff, Ff, pWhh + (size_t)G3F*Ff, pWhl + (size_t)G3F*Ff, Ff, gbh + G3F,
            pgh, nullptr, nullptr, G3F, Ff, nullptr);
        k_gru<<<gruBlocks, 256>>>(pgx1, pgh,
                                  pY + Bb*Ff, pYhi + Bb*Ff, pYlo + Bb*Ff,
                                  pouthi + (size_t)t*Bb*Ff, poutlo + (size_t)t*Bb*Ff);
    }

    // regressor
    k_mgemm<EPI_LRELU><<<dim3(128/BN, (Ss*Bb)/BM), 128, SMEM_TOTAL>>>(
        pouthi, poutlo, Ff, prW1h, prW1l, Ff, rb1,
        phid, nullptr, nullptr, 128, Ff, nullptr);
    k_pose<<<(Ss*Bb*6 + 127)/128, 128>>>(rW2, rb2, (float*)d_out);

    if (out_size >= Ss*Bb*6 + MB*Ff)
        k_copyY<<<768, 256>>>((float*)d_out + Ss*Bb*6);
}

// round 4
// speedup vs baseline: 4.5538x; 1.7597x over previous
#include <cuda_runtime.h>
#include <cuda_fp16.h>
#include <math.h>
#include <stdint.h>

// ---------------- problem constants ----------------
#define Bb   256
#define Ss   32
#define VFd  512
#define IFd  256
#define Ff   768
#define Hh   1024
#define Ll   2
#define Kk   8
#define MB   (Ll*Bb)
#define G3F  (3*Ff)

// ---------------- GEMM tiling ----------------
#define BM 64
#define BN 64
#define BK 32
#define ROWB   80            // smem row stride in bytes (40 halves = 5x16B, conflict-free)
#define PLANE  (64*ROWB)     // 5120 B, one 64x32 fp16 tile
#define STAGE_BYTES (2*PLANE) // A,B = 10240 B
#define NSTAGE 4
#define SMEM_TOTAL (NSTAGE*STAGE_BYTES)  // 40960

// ---------------- persistent device scratch ----------------
__device__ __align__(16) float g_dt  [Ss*Bb];
__device__ __align__(16) float g_Y   [MB*Ff];        // fp32 master ODE state
__device__ __align__(16) __half g_Yh [MB*Ff];
__device__ __align__(16) __half g_xh [Ss*Bb*Ff];
__device__ __align__(16) __half g_h1 [MB*Hh];
__device__ __align__(16) __half g_h2 [MB*Hh];
__device__ __align__(16) __half g_x1 [Bb*Ff];
__device__ __align__(16) __half g_out[Ss*Bb*Ff];
__device__ __align__(16) float g_gx0 [Ss*Bb*G3F];
__device__ __align__(16) float g_gh  [Bb*G3F];
__device__ __align__(16) float g_gx1 [Bb*G3F];
__device__ __align__(16) float g_hid [Ss*Bb*128];
// fp16 weights
__device__ __align__(16) __half g_W0[Hh*Ff];
__device__ __align__(16) __half g_W1[Hh*Hh];
__device__ __align__(16) __half g_W2[Ff*Hh];
__device__ __align__(16) __half g_Wx[Ll*G3F*Ff];
__device__ __align__(16) __half g_Wh[Ll*G3F*Ff];
__device__ __align__(16) __half g_rW1c[128*Ff];

__device__ __forceinline__ uint32_t smem_u32(const void* p) {
    uint32_t a;
    asm("{ .reg .u64 t; cvta.to.shared.u64 t, %1; cvt.u32.u64 %0, t; }" : "=r"(a) : "l"(p));
    return a;
}
__device__ __forceinline__ void cp16(uint32_t dst, const void* src) {
    asm volatile("cp.async.cg.shared.global [%0], [%1], 16;" :: "r"(dst), "l"(src));
}
__device__ __forceinline__ void ldm_x4(uint32_t addr, uint32_t r[4]) {
    asm volatile("ldmatrix.sync.aligned.m8n8.x4.shared.b16 {%0,%1,%2,%3}, [%4];"
                 : "=r"(r[0]), "=r"(r[1]), "=r"(r[2]), "=r"(r[3]) : "r"(addr));
}
__device__ __forceinline__ void mma16816(float d[4], const uint32_t a[4],
                                         uint32_t b0, uint32_t b1) {
    asm volatile("mma.sync.aligned.m16n8k16.row.col.f32.f16.f16.f32 "
                 "{%0,%1,%2,%3}, {%4,%5,%6,%7}, {%8,%9}, {%0,%1,%2,%3};"
                 : "+f"(d[0]), "+f"(d[1]), "+f"(d[2]), "+f"(d[3])
                 : "r"(a[0]), "r"(a[1]), "r"(a[2]), "r"(a[3]), "r"(b0), "r"(b1));
}

// ---------------- prep kernels ----------------
__global__ void k_cvt(const float* __restrict__ src, __half* __restrict__ dst, int n) {
    int stride = gridDim.x * blockDim.x;
    for (int i = blockIdx.x*blockDim.x + threadIdx.x; i < n; i += stride)
        dst[i] = __float2half_rn(src[i]);
}

__global__ void k_prep_x(const float* __restrict__ fv, const float* __restrict__ fi) {
    int stride = gridDim.x * blockDim.x;
    int total  = Ss*Bb*Ff;
    for (int idx = blockIdx.x*blockDim.x + threadIdx.x; idx < total; idx += stride) {
        int f  = idx % Ff;
        int sb = idx / Ff;
        int b  = sb % Bb, s = sb / Bb;
        float v = (f < VFd) ? fv[(b*Ss + s)*VFd + f] : fi[(b*Ss + s)*IFd + (f - VFd)];
        g_xh[idx] = __float2half_rn(v);
    }
}

__global__ void k_prep_misc(const float* __restrict__ ts) {
    int stride = gridDim.x * blockDim.x;
    for (int i = blockIdx.x*blockDim.x + threadIdx.x; i < MB*Ff; i += stride) {
        g_Y[i] = 0.0f; g_Yh[i] = __float2half(0.0f);
    }
    for (int i = blockIdx.x*blockDim.x + threadIdx.x; i < Ss*Bb; i += stride) {
        int s = i / Bb, b = i % Bb;
        g_dt[i] = (s < Ss-1) ? (ts[b*Ss + s + 1] - ts[b*Ss + s]) : 0.0f;
    }
}

// ---------------- fp16 HMMA GEMM: C[M,N] = epi(A*B^T + bias) ----------------
// A [M,K] fp16 row-major, B [N,K] fp16 row-major.
enum { EPI_STORE = 0, EPI_TANH = 1, EPI_ODE = 2, EPI_LRELU = 3 };

template<int EPI>
__global__ void __launch_bounds__(128)
k_mgemm(const __half* __restrict__ A, int lda,
        const __half* __restrict__ Bm, int ldb,
        const float* __restrict__ bias,
        float* __restrict__ Cf, __half* __restrict__ Ch,
        int ldc, int Kd, const float* __restrict__ dtv)
{
    extern __shared__ char smem[];
    const uint32_t smem_base = smem_u32(smem);
    const int tid  = threadIdx.x;
    const int wid  = tid >> 5, lane = tid & 31;
    const int m0   = blockIdx.y << 6, n0 = blockIdx.x << 6;
    const int warp_m = wid & 1, warp_n = wid >> 1;

    const int l_row0 = tid >> 2;            // 0..31
    const int l_kq   = (tid & 3) * 8;       // 0,8,16,24

    auto issue_stage = [&](int c) {
        const int k0 = c * BK;
        const uint32_t sb = smem_base + (uint32_t)(c % NSTAGE) * STAGE_BYTES;
#pragma unroll
        for (int i = 0; i < 2; i++) {
            const int row = l_row0 + i * 32;
            const uint32_t dst = sb + (uint32_t)row * ROWB + l_kq * 2;
            cp16(dst,         A  + (size_t)(m0 + row) * lda + k0 + l_kq);
            cp16(dst + PLANE, Bm + (size_t)(n0 + row) * ldb + k0 + l_kq);
        }
        asm volatile("cp.async.commit_group;");
    };

    float acc[2][4][4];
#pragma unroll
    for (int mi = 0; mi < 2; mi++)
#pragma unroll
        for (int nj = 0; nj < 4; nj++)
#pragma unroll
            for (int e = 0; e < 4; e++) acc[mi][nj][e] = 0.0f;

    const int nc = Kd / BK;
    issue_stage(0);
    issue_stage(1);
    if (nc > 2) issue_stage(2);

    const int arow  = lane & 15, acol8 = (lane >> 4) * 8;
    const int brow  = ((lane >> 4) & 1) * 8 + (lane & 7);
    const int bcol8 = ((lane >> 3) & 1) * 8;
    const uint32_t aoff = (uint32_t)(warp_m*32 + arow) * ROWB + acol8 * 2;
    const uint32_t boff = PLANE + (uint32_t)(warp_n*32 + brow) * ROWB + bcol8 * 2;

    for (int c = 0; c < nc; c++) {
        if (c + 2 < nc)      { asm volatile("cp.async.wait_group 2;"); }
        else if (c + 1 < nc) { asm volatile("cp.async.wait_group 1;"); }
        else                 { asm volatile("cp.async.wait_group 0;"); }
        __syncthreads();
        if (c + 3 < nc) issue_stage(c + 3);

        const uint32_t sb = smem_base + (uint32_t)(c % NSTAGE) * STAGE_BYTES;
#pragma unroll
        for (int kk = 0; kk < 2; kk++) {
            uint32_t ah[2][4], bh[2][4];
#pragma unroll
            for (int mi = 0; mi < 2; mi++)
                ldm_x4(sb + aoff + mi*16*ROWB + kk*32, ah[mi]);
#pragma unroll
            for (int nj = 0; nj < 2; nj++)
                ldm_x4(sb + boff + nj*16*ROWB + kk*32, bh[nj]);
#pragma unroll
            for (int mi = 0; mi < 2; mi++)
#pragma unroll
                for (int n8 = 0; n8 < 4; n8++) {
                    const int nj = n8 >> 1, hf = (n8 & 1) << 1;
                    mma16816(acc[mi][n8], ah[mi], bh[nj][hf], bh[nj][hf+1]);
                }
        }
        __syncthreads();
    }

    // ---- epilogue ----
    const int rbase = lane >> 2;
    const int cbase = (lane & 3) * 2;
#pragma unroll
    for (int mi = 0; mi < 2; mi++) {
#pragma unroll
        for (int n8 = 0; n8 < 4; n8++) {
#pragma unroll
            for (int half = 0; half < 2; half++) {
                const int m = m0 + warp_m*32 + mi*16 + rbase + half*8;
                const int n = n0 + warp_n*32 + n8*8 + cbase;
                float v0 = acc[mi][n8][half*2 + 0] + __ldg(bias + n);
                float v1 = acc[mi][n8][half*2 + 1] + __ldg(bias + n + 1);
                if (EPI == EPI_TANH)  { v0 = tanhf(v0); v1 = tanhf(v1); }
                if (EPI == EPI_LRELU) { v0 = (v0 > 0.f) ? v0 : 0.1f*v0;
                                        v1 = (v1 > 0.f) ? v1 : 0.1f*v1; }
                const size_t o = (size_t)m * ldc + n;
                if (EPI == EPI_ODE) {
                    const float sub = __ldg(dtv + (m & (Bb - 1))) * (1.0f / Kk);
                    float2 y = *(float2*)(Cf + o);
                    y.x += sub * v0; y.y += sub * v1;
                    *(float2*)(Cf + o) = y;
                    *(__half2*)(Ch + o) = __floats2half2_rn(y.x, y.y);
                } else if (EPI == EPI_TANH) {
                    *(__half2*)(Ch + o) = __floats2half2_rn(v0, v1);
                } else {
                    *(float2*)(Cf + o) = make_float2(v0, v1);
                }
            }
        }
    }
}

// ---------------- GRU elementwise combine ----------------
__global__ void k_gru(const float* __restrict__ gx, const float* __restrict__ gh,
                      float* __restrict__ h, __half* __restrict__ hh,
                      __half* __restrict__ xh)
{
    int idx = blockIdx.x*blockDim.x + threadIdx.x;
    if (idx >= Bb*Ff) return;
    int b = idx / Ff, f = idx % Ff;
    int o = b*G3F + f;
    float r  = 1.0f / (1.0f + expf(-(gx[o]        + gh[o]       )));
    float z  = 1.0f / (1.0f + expf(-(gx[o + Ff]   + gh[o + Ff]  )));
    float n  = tanhf(gx[o + 2*Ff] + r * gh[o + 2*Ff]);
    float hn = (1.0f - z) * n + z * h[idx];
    h[idx] = hn;
    __half hv = __float2half_rn(hn);
    hh[idx] = hv;
    xh[idx] = hv;
}

// ---------------- regressor second layer (N=6) ----------------
__global__ void k_pose(const float* __restrict__ W2, const float* __restrict__ b2,
                       float* __restrict__ outp)
{
    int idx = blockIdx.x*blockDim.x + threadIdx.x;
    if (idx >= Ss*Bb*6) return;
    int n = idx % 6;
    int m = idx / 6;
    int b = m % Bb, s = m / Bb;
    const float* hrow = g_hid + (size_t)m * 128;
    const float* wrow = W2 + n * 128;
    float acc = b2[n];
#pragma unroll 8
    for (int k = 0; k < 128; k++) acc += hrow[k] * wrow[k];
    outp[(b*Ss + s)*6 + n] = acc;
}

__global__ void k_copyY(float* __restrict__ outp) {
    int stride = gridDim.x * blockDim.x;
    for (int i = blockIdx.x*blockDim.x + threadIdx.x; i < MB*Ff; i += stride)
        outp[i] = g_Y[i];
}

// ---------------- launch ----------------
extern "C" void kernel_launch(void* const* d_in, const int* in_sizes, int n_in,
                              void* d_out, int out_size)
{
    const float* fv  = (const float*)d_in[0];
    const float* fi  = (const float*)d_in[1];
    const float* ts  = (const float*)d_in[2];
    const float* W0  = (const float*)d_in[3];
    const float* b0  = (const float*)d_in[4];
    const float* W1  = (const float*)d_in[5];
    const float* b1  = (const float*)d_in[6];
    const float* W2o = (const float*)d_in[7];
    const float* b2o = (const float*)d_in[8];
    const float* gWx = (const float*)d_in[9];
    const float* gWh = (const float*)d_in[10];
    const float* gbx = (const float*)d_in[11];
    const float* gbh = (const float*)d_in[12];
    const float* rW1 = (const float*)d_in[13];
    const float* rb1 = (const float*)d_in[14];
    const float* rW2 = (const float*)d_in[15];
    const float* rb2 = (const float*)d_in[16];

    cudaFuncSetAttribute(k_mgemm<EPI_STORE>, cudaFuncAttributeMaxDynamicSharedMemorySize, SMEM_TOTAL);
    cudaFuncSetAttribute(k_mgemm<EPI_TANH >, cudaFuncAttributeMaxDynamicSharedMemorySize, SMEM_TOTAL);
    cudaFuncSetAttribute(k_mgemm<EPI_ODE  >, cudaFuncAttributeMaxDynamicSharedMemorySize, SMEM_TOTAL);
    cudaFuncSetAttribute(k_mgemm<EPI_LRELU>, cudaFuncAttributeMaxDynamicSharedMemorySize, SMEM_TOTAL);

#define SYM(p, s) float* p; cudaGetSymbolAddress((void**)&p, s)
#define SYMH(p, s) __half* p; cudaGetSymbolAddress((void**)&p, s)
    SYM(pdt, g_dt); SYM(pY, g_Y);
    SYMH(pYh, g_Yh); SYMH(pxh, g_xh);
    SYMH(ph1, g_h1); SYMH(ph2, g_h2); SYMH(px1, g_x1); SYMH(pout, g_out);
    SYM(pgx0, g_gx0); SYM(pgh, g_gh); SYM(pgx1, g_gx1); SYM(phid, g_hid);
    SYMH(pW0, g_W0); SYMH(pW1, g_W1); SYMH(pW2, g_W2);
    SYMH(pWx, g_Wx); SYMH(pWh, g_Wh); SYMH(prW1, g_rW1c);
#undef SYM
#undef SYMH

    // weight conversions (deterministic; recomputed every call)
    k_cvt<<<256, 256>>>(W0,  pW0,  Hh*Ff);
    k_cvt<<<256, 256>>>(W1,  pW1,  Hh*Hh);
    k_cvt<<<256, 256>>>(W2o, pW2,  Ff*Hh);
    k_cvt<<<256, 256>>>(gWx, pWx,  Ll*G3F*Ff);
    k_cvt<<<256, 256>>>(gWh, pWh,  Ll*G3F*Ff);
    k_cvt<<<64,  256>>>(rW1, prW1, 128*Ff);

    k_prep_x<<<512, 256>>>(fv, fi);
    k_prep_misc<<<512, 256>>>(ts);

    // hoisted layer-0 GRU input projection: gx0[S*B,3F] = x @ Wx0^T + bx0
    k_mgemm<EPI_STORE><<<dim3(G3F/BN, (Ss*Bb)/BM), 128, SMEM_TOTAL>>>(
        pxh, Ff, pWx, Ff, gbx, pgx0, nullptr, G3F, Ff, nullptr);

    const int gruBlocks = (Bb*Ff + 255) / 256;

    for (int t = 0; t < Ss; t++) {
        for (int k = 0; k < Kk; k++) {
            k_mgemm<EPI_TANH><<<dim3(Hh/BN, MB/BM), 128, SMEM_TOTAL>>>(
                pYh, Ff, pW0, Ff, b0, nullptr, ph1, Hh, Ff, nullptr);
            k_mgemm<EPI_TANH><<<dim3(Hh/BN, MB/BM), 128, SMEM_TOTAL>>>(
                ph1, Hh, pW1, Hh, b1, nullptr, ph2, Hh, Hh, nullptr);
            k_mgemm<EPI_ODE><<<dim3(Ff/BN, MB/BM), 128, SMEM_TOTAL>>>(
                ph2, Hh, pW2, Hh, b2o, pY, pYh, Ff, Hh, pdt + t*Bb);
        }
        // GRU layer 0
        k_mgemm<EPI_STORE><<<dim3(G3F/BN, Bb/BM), 128, SMEM_TOTAL>>>(
            pYh, Ff, pWh, Ff, gbh, pgh, nullptr, G3F, Ff, nullptr);
        k_gru<<<gruBlocks, 256>>>(pgx0 + (size_t)t*Bb*G3F, pgh, pY, pYh, px1);
        // GRU layer 1
        k_mgemm<EPI_STORE><<<dim3(G3F/BN, Bb/BM), 128, SMEM_TOTAL>>>(
            px1, Ff, pWx + (size_t)G3F*Ff, Ff, gbx + G3F, pgx1, nullptr, G3F, Ff, nullptr);
        k_mgemm<EPI_STORE><<<dim3(G3F/BN, Bb/BM), 128, SMEM_TOTAL>>>(
            pYh + Bb*Ff, Ff, pWh + (size_t)G3F*Ff, Ff, gbh + G3F, pgh, nullptr, G3F, Ff, nullptr);
        k_gru<<<gruBlocks, 256>>>(pgx1, pgh, pY + Bb*Ff, pYh + Bb*Ff,
                                  pout + (size_t)t*Bb*Ff);
    }

    // regressor
    k_mgemm<EPI_LRELU><<<dim3(128/BN, (Ss*Bb)/BM), 128, SMEM_TOTAL>>>(
        pout, Ff, prW1, Ff, rb1, phid, nullptr, 128, Ff, nullptr);
    k_pose<<<(Ss*Bb*6 + 127)/128, 128>>>(rW2, rb2, (float*)d_out);

    if (out_size >= Ss*Bb*6 + MB*Ff)
        k_copyY<<<768, 256>>>((float*)d_out + Ss*Bb*6);
}